// round 5
// baseline (speedup 1.0000x reference)
#include <cuda_runtime.h>
#include <math.h>

// Problem constants
#define BB 4
#define NN 32768
#define KK 16
#define IN_DIM 32
#define HID 64
#define OUT_DIM 32
#define KIN 36
#define KH 64

typedef unsigned long long ull;

// Scratch for pointwise-MLP output x: (B, N, 32) floats = 16 MB
__device__ float g_x[BB * NN * OUT_DIM];

// Constant-bank copies (LDC port). Smem + global(L1) carry the other 2/3.
__constant__ ulonglong2 cWk1[KIN * KH / 4];       //  9216 B
__constant__ ulonglong2 cWk2[KH * KH / 4];        // 16384 B
__constant__ ulonglong2 cWk3[KH * OUT_DIM / 4];   //  8192 B
__constant__ float  cbk1[KH];
__constant__ float  cbk2[KH];
__constant__ float  cbk3[OUT_DIM];
__constant__ float  cG[OUT_DIM];
__constant__ float  cBt[OUT_DIM];
__constant__ ulonglong2 cWp1[IN_DIM * HID / 4];   //  8192 B
__constant__ ulonglong2 cWp2[HID * OUT_DIM / 4];  //  8192 B
__constant__ float  cbp1[HID];
__constant__ float  cbp2[OUT_DIM];

// Packed f32x2 helpers (FFMA2 — PTX-only)
__device__ __forceinline__ ull ffma2(ull a, ull b, ull c) {
    ull d;
    asm("fma.rn.f32x2 %0, %1, %2, %3;" : "=l"(d) : "l"(a), "l"(b), "l"(c));
    return d;
}
__device__ __forceinline__ ull fadd2(ull a, ull b) {
    ull d;
    asm("add.rn.f32x2 %0, %1, %2;" : "=l"(d) : "l"(a), "l"(b));
    return d;
}
__device__ __forceinline__ ull pack_dup(float v) {
    ull d;
    asm("mov.b64 %0, {%1, %1};" : "=l"(d) : "r"(__float_as_uint(v)));
    return d;
}
__device__ __forceinline__ ull pack2(float lo, float hi) {
    ull d;
    asm("mov.b64 %0, {%1, %2};" : "=l"(d) : "r"(__float_as_uint(lo)), "r"(__float_as_uint(hi)));
    return d;
}
__device__ __forceinline__ void unpack2(ull p, float& lo, float& hi) {
    unsigned int a, b;
    asm("mov.b64 {%0, %1}, %2;" : "=r"(a), "=r"(b) : "l"(p));
    lo = __uint_as_float(a); hi = __uint_as_float(b);
}

__device__ __forceinline__ float gelu_exact(float v) {
    return 0.5f * v * (1.0f + erff(v * 0.7071067811865476f));
}

// ---------------------------------------------------------------------------
// Kernel 1: pointwise MLP (packed math; weights alternate const / global-L1)
// ---------------------------------------------------------------------------
__global__ __launch_bounds__(256) void pointwise_kernel(
    const float* __restrict__ inp,
    const float* __restrict__ Wp1g,
    const float* __restrict__ Wp2g)
{
    const ulonglong2* __restrict__ gW1 = (const ulonglong2*)Wp1g;
    const ulonglong2* __restrict__ gW2 = (const ulonglong2*)Wp2g;

    int t = blockIdx.x * 256 + threadIdx.x;   // 0 .. B*N-1
    const float4* ir = (const float4*)(inp + t * IN_DIM);

    float in[IN_DIM];
#pragma unroll
    for (int i = 0; i < IN_DIM / 4; ++i) {
        float4 v = ir[i];
        in[4*i+0] = v.x; in[4*i+1] = v.y; in[4*i+2] = v.z; in[4*i+3] = v.w;
    }

    ull acc[HID/2];
#pragma unroll
    for (int i = 0; i < HID/2; ++i) acc[i] = pack2(cbp1[2*i], cbp1[2*i+1]);
#pragma unroll
    for (int c = 0; c < IN_DIM; ++c) {
        ull v = pack_dup(in[c]);
#pragma unroll
        for (int o2 = 0; o2 < HID/4; ++o2) {
            int idx = c * (HID/4) + o2;
            ulonglong2 w = (c & 1) ? gW1[idx] : cWp1[idx];
            acc[2*o2+0] = ffma2(v, w.x, acc[2*o2+0]);
            acc[2*o2+1] = ffma2(v, w.y, acc[2*o2+1]);
        }
    }
    float h[HID];
#pragma unroll
    for (int i = 0; i < HID/2; ++i) {
        float a, b; unpack2(acc[i], a, b);
        h[2*i] = gelu_exact(a); h[2*i+1] = gelu_exact(b);
    }

    ull acc2[OUT_DIM/2];
#pragma unroll
    for (int i = 0; i < OUT_DIM/2; ++i) acc2[i] = pack2(cbp2[2*i], cbp2[2*i+1]);
#pragma unroll
    for (int c = 0; c < HID; ++c) {
        ull v = pack_dup(h[c]);
#pragma unroll
        for (int o2 = 0; o2 < OUT_DIM/4; ++o2) {
            int idx = c * (OUT_DIM/4) + o2;
            ulonglong2 w = (c & 1) ? gW2[idx] : cWp2[idx];
            acc2[2*o2+0] = ffma2(v, w.x, acc2[2*o2+0]);
            acc2[2*o2+1] = ffma2(v, w.y, acc2[2*o2+1]);
        }
    }
    ulonglong2* xr = (ulonglong2*)(g_x + t * OUT_DIM);
#pragma unroll
    for (int o2 = 0; o2 < OUT_DIM/4; ++o2) {
        ulonglong2 r; r.x = acc2[2*o2+0]; r.y = acc2[2*o2+1];
        xr[o2] = r;
    }
}

// ---------------------------------------------------------------------------
// Kernel 2: edge MLP. Weight loads rotate over THREE ports on c%3:
//   0 -> constant bank (LDC), 1 -> shared (LDS), 2 -> global L1 (LDG).
// Port time per 48B: max(8,8,~5) = 8 cyc < fma 12 cyc -> fma-bound.
// Register-lean (<=128 regs -> 4 CTAs/SM); layers 2+3 fused.
// ---------------------------------------------------------------------------
__global__ __launch_bounds__(128, 4) void edge_kernel(
    const float* __restrict__ igrid,   // (N,2)
    const float* __restrict__ ogrid,   // (N,2)
    const int*   __restrict__ nidx,    // (N,16)
    const float* __restrict__ Wk1,
    const float* __restrict__ Wk2,
    const float* __restrict__ Wk3,
    float* __restrict__ out)
{
    __shared__ ulonglong2 sW1[KIN * KH / 4];      //  9216 B
    __shared__ ulonglong2 sW2[KH * KH / 4];       // 16384 B
    __shared__ ulonglong2 sW3[KH * OUT_DIM / 4];  //  8192 B

    const ulonglong2* __restrict__ gW1 = (const ulonglong2*)Wk1;
    const ulonglong2* __restrict__ gW2 = (const ulonglong2*)Wk2;
    const ulonglong2* __restrict__ gW3 = (const ulonglong2*)Wk3;

    int tid = threadIdx.x;
    {
        for (int i = tid; i < KIN * KH / 4; i += 128) sW1[i] = gW1[i];
        for (int i = tid; i < KH * KH / 4; i += 128) sW2[i] = gW2[i];
        for (int i = tid; i < KH * OUT_DIM / 4; i += 128) sW3[i] = gW3[i];
    }
    __syncthreads();

    int r = tid >> 4;                // node within block (0..7)
    int k = tid & 15;                // neighbor index (0..15)
    int bn = blockIdx.x * 8 + r;     // 0 .. B*N-1
    int b  = bn >> 15;               // / 32768
    int n  = bn & (NN - 1);

    int nb = nidx[n * KK + k];

    float h1[KH];   // after layer 1; before that, first 36 slots hold agg

    // agg = [input_grid[nb], output_grid[n], f_y(32)]  (stored in h1[0..35])
    {
        h1[0] = igrid[nb * 2 + 0];
        h1[1] = igrid[nb * 2 + 1];
        h1[2] = ogrid[n * 2 + 0];
        h1[3] = ogrid[n * 2 + 1];
        const float4* xr = (const float4*)(g_x + (b * NN + nb) * OUT_DIM);
#pragma unroll
        for (int i = 0; i < OUT_DIM / 4; ++i) {
            float4 v = xr[i];
            h1[4 + 4*i + 0] = v.x; h1[4 + 4*i + 1] = v.y;
            h1[4 + 4*i + 2] = v.z; h1[4 + 4*i + 3] = v.w;
        }
    }

    // ---- Layer 1: 36 -> 64, gelu; two output chunks of 32 channels.
    {
        float agg[KIN];
#pragma unroll
        for (int i = 0; i < KIN; ++i) agg[i] = h1[i];

#pragma unroll
        for (int ch = 1; ch >= 0; --ch) {
            ull acc[16];
#pragma unroll
            for (int i = 0; i < 16; ++i)
                acc[i] = pack2(cbk1[32*ch + 2*i], cbk1[32*ch + 2*i + 1]);
#pragma unroll
            for (int c = 0; c < KIN; ++c) {
                ull v = pack_dup(agg[c]);
#pragma unroll
                for (int o2 = 0; o2 < 8; ++o2) {
                    int idx = c * (KH/4) + ch * 8 + o2;
                    int m = c % 3;
                    ulonglong2 w;
                    if (m == 0)      w = cWk1[idx];
                    else if (m == 1) w = sW1[idx];
                    else             w = gW1[idx];
                    acc[2*o2+0] = ffma2(v, w.x, acc[2*o2+0]);
                    acc[2*o2+1] = ffma2(v, w.y, acc[2*o2+1]);
                }
            }
#pragma unroll
            for (int i = 0; i < 16; ++i) {
                float a, bq; unpack2(acc[i], a, bq);
                h1[32*ch + 2*i]     = gelu_exact(a);
                h1[32*ch + 2*i + 1] = gelu_exact(bq);
            }
        }
    }

    // ---- Layers 2+3 fused: 8 h2-channels per chunk -> straight into kacc.
    ull kacc[OUT_DIM/2];
#pragma unroll
    for (int i = 0; i < OUT_DIM/2; ++i) kacc[i] = pack2(cbk3[2*i], cbk3[2*i+1]);

#pragma unroll
    for (int ch = 0; ch < 8; ++ch) {
        ull acc[4];
#pragma unroll
        for (int i = 0; i < 4; ++i)
            acc[i] = pack2(cbk2[8*ch + 2*i], cbk2[8*ch + 2*i + 1]);
#pragma unroll
        for (int c = 0; c < KH; ++c) {
            ull v = pack_dup(h1[c]);
#pragma unroll
            for (int o2 = 0; o2 < 2; ++o2) {
                int idx = c * (KH/4) + ch * 2 + o2;
                int m = c % 3;
                ulonglong2 w;
                if (m == 0)      w = cWk2[idx];
                else if (m == 1) w = sW2[idx];
                else             w = gW2[idx];
                acc[2*o2+0] = ffma2(v, w.x, acc[2*o2+0]);
                acc[2*o2+1] = ffma2(v, w.y, acc[2*o2+1]);
            }
        }
        float t[8];
#pragma unroll
        for (int i = 0; i < 4; ++i) {
            float a, bq; unpack2(acc[i], a, bq);
            t[2*i] = gelu_exact(a); t[2*i+1] = gelu_exact(bq);
        }
        // Stream these 8 h2-channels into the layer-3 accumulators
#pragma unroll
        for (int cc = 0; cc < 8; ++cc) {
            int c3 = 8*ch + cc;
            ull v = pack_dup(t[cc]);
#pragma unroll
            for (int o2 = 0; o2 < OUT_DIM/4; ++o2) {
                int idx = c3 * (OUT_DIM/4) + o2;
                int m = c3 % 3;
                ulonglong2 w;
                if (m == 0)      w = cWk3[idx];
                else if (m == 1) w = sW3[idx];
                else             w = gW3[idx];
                kacc[2*o2+0] = ffma2(v, w.x, kacc[2*o2+0]);
                kacc[2*o2+1] = ffma2(v, w.y, kacc[2*o2+1]);
            }
        }
    }

    // Mean over K via packed shfl butterfly (16 lanes per node)
#pragma unroll
    for (int off = 8; off >= 1; off >>= 1) {
#pragma unroll
        for (int i = 0; i < OUT_DIM/2; ++i) {
            ull other = __shfl_xor_sync(0xffffffffu, kacc[i], off);
            kacc[i] = fadd2(kacc[i], other);
        }
    }

    // Lane 0 of each 16-lane group: mean, residual, LayerNorm, store
    if (k == 0) {
        float kout[OUT_DIM];
#pragma unroll
        for (int i = 0; i < OUT_DIM/2; ++i) unpack2(kacc[i], kout[2*i], kout[2*i+1]);

        float o[OUT_DIM];
        const float4* xr = (const float4*)(g_x + bn * OUT_DIM);
        float sum = 0.0f;
#pragma unroll
        for (int i = 0; i < OUT_DIM / 4; ++i) {
            float4 v = xr[i];
            o[4*i+0] = fmaf(kout[4*i+0], 0.0625f, v.x);
            o[4*i+1] = fmaf(kout[4*i+1], 0.0625f, v.y);
            o[4*i+2] = fmaf(kout[4*i+2], 0.0625f, v.z);
            o[4*i+3] = fmaf(kout[4*i+3], 0.0625f, v.w);
            sum += o[4*i+0] + o[4*i+1] + o[4*i+2] + o[4*i+3];
        }
        float mu = sum * (1.0f / OUT_DIM);
        float vs = 0.0f;
#pragma unroll
        for (int i = 0; i < OUT_DIM; ++i) {
            float d = o[i] - mu;
            vs = fmaf(d, d, vs);
        }
        float rs = rsqrtf(vs * (1.0f / OUT_DIM) + 1e-5f);

        float4* op = (float4*)(out + bn * OUT_DIM);
#pragma unroll
        for (int i = 0; i < OUT_DIM / 4; ++i) {
            float4 w;
            w.x = fmaf((o[4*i+0] - mu) * rs, cG[4*i+0], cBt[4*i+0]);
            w.y = fmaf((o[4*i+1] - mu) * rs, cG[4*i+1], cBt[4*i+1]);
            w.z = fmaf((o[4*i+2] - mu) * rs, cG[4*i+2], cBt[4*i+2]);
            w.w = fmaf((o[4*i+3] - mu) * rs, cG[4*i+3], cBt[4*i+3]);
            op[i] = w;
        }
    }
}

// ---------------------------------------------------------------------------
extern "C" void kernel_launch(void* const* d_in, const int* in_sizes, int n_in,
                              void* d_out, int out_size) {
    const float* inp   = (const float*)d_in[0];
    const float* igrid = (const float*)d_in[1];
    const float* ogrid = (const float*)d_in[2];
    const int*   nidx  = (const int*)  d_in[3];
    const float* Wp1   = (const float*)d_in[4];
    const float* bp1   = (const float*)d_in[5];
    const float* Wp2   = (const float*)d_in[6];
    const float* bp2   = (const float*)d_in[7];
    const float* Wk1   = (const float*)d_in[8];
    const float* bk1   = (const float*)d_in[9];
    const float* Wk2   = (const float*)d_in[10];
    const float* bk2   = (const float*)d_in[11];
    const float* Wk3   = (const float*)d_in[12];
    const float* bk3   = (const float*)d_in[13];
    const float* ln_g  = (const float*)d_in[14];
    const float* ln_b  = (const float*)d_in[15];
    float* out = (float*)d_out;

    cudaMemcpyToSymbolAsync(cWk1, Wk1, KIN * KH * sizeof(float), 0, cudaMemcpyDeviceToDevice);
    cudaMemcpyToSymbolAsync(cWk2, Wk2, KH * KH * sizeof(float), 0, cudaMemcpyDeviceToDevice);
    cudaMemcpyToSymbolAsync(cWk3, Wk3, KH * OUT_DIM * sizeof(float), 0, cudaMemcpyDeviceToDevice);
    cudaMemcpyToSymbolAsync(cbk1, bk1, KH * sizeof(float), 0, cudaMemcpyDeviceToDevice);
    cudaMemcpyToSymbolAsync(cbk2, bk2, KH * sizeof(float), 0, cudaMemcpyDeviceToDevice);
    cudaMemcpyToSymbolAsync(cbk3, bk3, OUT_DIM * sizeof(float), 0, cudaMemcpyDeviceToDevice);
    cudaMemcpyToSymbolAsync(cG,   ln_g, OUT_DIM * sizeof(float), 0, cudaMemcpyDeviceToDevice);
    cudaMemcpyToSymbolAsync(cBt,  ln_b, OUT_DIM * sizeof(float), 0, cudaMemcpyDeviceToDevice);
    cudaMemcpyToSymbolAsync(cWp1, Wp1, IN_DIM * HID * sizeof(float), 0, cudaMemcpyDeviceToDevice);
    cudaMemcpyToSymbolAsync(cWp2, Wp2, HID * OUT_DIM * sizeof(float), 0, cudaMemcpyDeviceToDevice);
    cudaMemcpyToSymbolAsync(cbp1, bp1, HID * sizeof(float), 0, cudaMemcpyDeviceToDevice);
    cudaMemcpyToSymbolAsync(cbp2, bp2, OUT_DIM * sizeof(float), 0, cudaMemcpyDeviceToDevice);

    pointwise_kernel<<<(BB * NN) / 256, 256>>>(inp, Wp1, Wp2);
    edge_kernel<<<(BB * NN) / 8, 128>>>(igrid, ogrid, nidx, Wk1, Wk2, Wk3, out);
}

// round 6
// speedup vs baseline: 2.5055x; 2.5055x over previous
#include <cuda_runtime.h>
#include <math.h>
#include <stdint.h>

// Problem constants
#define BB 4
#define NN 32768
#define KK 16
#define IN_DIM 32
#define HID 64
#define OUT_DIM 32
#define KIN 36
#define KH 64

typedef unsigned long long ull;
typedef unsigned int uint;

// Scratch: pointwise-MLP output x (B,N,32) = 16 MB, + fragment-packed weights
__device__ float g_x[BB * NN * OUT_DIM];

// Fragment-packed tf32 weights (bit patterns stored as float):
//  W1: 5 ktiles x 8 ntiles, W2: 8x8, W3: 8x4; 64 words per tile (lane*2 + reg)
#define W1F_OFF 0
#define W1F_SIZE (5 * 8 * 64)     // 2560
#define W2F_OFF (W1F_OFF + W1F_SIZE)
#define W2F_SIZE (8 * 8 * 64)     // 4096
#define W3F_OFF (W2F_OFF + W2F_SIZE)
#define W3F_SIZE (8 * 4 * 64)     // 2048
#define WF_TOTAL (W3F_OFF + W3F_SIZE)  // 8704 floats
__device__ float g_wfrag[WF_TOTAL];

// Small params in constant bank
__constant__ float cbk1[KH];
__constant__ float cbk2[KH];
__constant__ float cbk3[OUT_DIM];
__constant__ float cG[OUT_DIM];
__constant__ float cBt[OUT_DIM];
__constant__ ulonglong2 cWp1[IN_DIM * HID / 4];
__constant__ ulonglong2 cWp2[HID * OUT_DIM / 4];
__constant__ float cbp1[HID];
__constant__ float cbp2[OUT_DIM];

// ---------------- helpers ----------------
__device__ __forceinline__ ull ffma2(ull a, ull b, ull c) {
    ull d;
    asm("fma.rn.f32x2 %0, %1, %2, %3;" : "=l"(d) : "l"(a), "l"(b), "l"(c));
    return d;
}
__device__ __forceinline__ ull pack_dup(float v) {
    ull d;
    asm("mov.b64 %0, {%1, %1};" : "=l"(d) : "r"(__float_as_uint(v)));
    return d;
}
__device__ __forceinline__ ull pack2(float lo, float hi) {
    ull d;
    asm("mov.b64 %0, {%1, %2};" : "=l"(d) : "r"(__float_as_uint(lo)), "r"(__float_as_uint(hi)));
    return d;
}
__device__ __forceinline__ void unpack2(ull p, float& lo, float& hi) {
    uint a, b;
    asm("mov.b64 {%0, %1}, %2;" : "=r"(a), "=r"(b) : "l"(p));
    lo = __uint_as_float(a); hi = __uint_as_float(b);
}
__device__ __forceinline__ float gelu_exact(float v) {
    return 0.5f * v * (1.0f + erff(v * 0.7071067811865476f));
}
__device__ __forceinline__ uint tf32cvt(float f) {
    uint u;
    asm("cvt.rna.tf32.f32 %0, %1;" : "=r"(u) : "f"(f));
    return u;
}
__device__ __forceinline__ void mma_tf32(
    float& c0, float& c1, float& c2, float& c3,
    uint a0, uint a1, uint a2, uint a3, uint b0, uint b1)
{
    asm("mma.sync.aligned.m16n8k8.row.col.f32.tf32.tf32.f32 "
        "{%0,%1,%2,%3}, {%4,%5,%6,%7}, {%8,%9}, {%0,%1,%2,%3};"
        : "+f"(c0), "+f"(c1), "+f"(c2), "+f"(c3)
        : "r"(a0), "r"(a1), "r"(a2), "r"(a3), "r"(b0), "r"(b1));
}

// ---------------------------------------------------------------------------
// Kernel 0: pack weights into mma B-fragment order (tf32), one-time per launch.
// B frag (m16n8k8): b0: k=lane%4, n=lane/4;  b1: k=lane%4+4, n=lane/4.
// Word within tile = lane*2 + reg  (so LDS.64 per lane gives {b0,b1}).
// ---------------------------------------------------------------------------
__global__ void pack_weights(const float* __restrict__ Wk1,
                             const float* __restrict__ Wk2,
                             const float* __restrict__ Wk3)
{
    int tid = threadIdx.x;
    for (int i = tid; i < W1F_SIZE; i += 256) {
        int tile = i >> 6, r2 = i & 63, lane = r2 >> 1, reg = r2 & 1;
        int kt = tile >> 3, nt = tile & 7;
        int k = kt * 8 + (lane & 3) + reg * 4;
        int n = nt * 8 + (lane >> 2);
        float v = (k < KIN) ? Wk1[k * KH + n] : 0.0f;
        g_wfrag[W1F_OFF + i] = __uint_as_float(tf32cvt(v));
    }
    for (int i = tid; i < W2F_SIZE; i += 256) {
        int tile = i >> 6, r2 = i & 63, lane = r2 >> 1, reg = r2 & 1;
        int kt = tile >> 3, nt = tile & 7;
        int k = kt * 8 + (lane & 3) + reg * 4;
        int n = nt * 8 + (lane >> 2);
        g_wfrag[W2F_OFF + i] = __uint_as_float(tf32cvt(Wk2[k * KH + n]));
    }
    for (int i = tid; i < W3F_SIZE; i += 256) {
        int tile = i >> 6, r2 = i & 63, lane = r2 >> 1, reg = r2 & 1;
        int kt = tile >> 2, nt = tile & 3;
        int k = kt * 8 + (lane & 3) + reg * 4;
        int n = nt * 8 + (lane >> 2);
        g_wfrag[W3F_OFF + i] = __uint_as_float(tf32cvt(Wk3[k * OUT_DIM + n]));
    }
}

// ---------------------------------------------------------------------------
// Kernel 1: pointwise MLP (FFMA2, const weights) — unchanged from R4
// ---------------------------------------------------------------------------
__global__ __launch_bounds__(256) void pointwise_kernel(
    const float* __restrict__ inp)
{
    int t = blockIdx.x * 256 + threadIdx.x;
    const float4* ir = (const float4*)(inp + t * IN_DIM);

    float in[IN_DIM];
#pragma unroll
    for (int i = 0; i < IN_DIM / 4; ++i) {
        float4 v = ir[i];
        in[4*i+0] = v.x; in[4*i+1] = v.y; in[4*i+2] = v.z; in[4*i+3] = v.w;
    }

    ull acc[HID/2];
#pragma unroll
    for (int i = 0; i < HID/2; ++i) acc[i] = pack2(cbp1[2*i], cbp1[2*i+1]);
#pragma unroll
    for (int c = 0; c < IN_DIM; ++c) {
        ull v = pack_dup(in[c]);
#pragma unroll
        for (int o2 = 0; o2 < HID/4; ++o2) {
            ulonglong2 w = cWp1[c * (HID/4) + o2];
            acc[2*o2+0] = ffma2(v, w.x, acc[2*o2+0]);
            acc[2*o2+1] = ffma2(v, w.y, acc[2*o2+1]);
        }
    }
    float h[HID];
#pragma unroll
    for (int i = 0; i < HID/2; ++i) {
        float a, b; unpack2(acc[i], a, b);
        h[2*i] = gelu_exact(a); h[2*i+1] = gelu_exact(b);
    }

    ull acc2[OUT_DIM/2];
#pragma unroll
    for (int i = 0; i < OUT_DIM/2; ++i) acc2[i] = pack2(cbp2[2*i], cbp2[2*i+1]);
#pragma unroll
    for (int c = 0; c < HID; ++c) {
        ull v = pack_dup(h[c]);
#pragma unroll
        for (int o2 = 0; o2 < OUT_DIM/4; ++o2) {
            ulonglong2 w = cWp2[c * (OUT_DIM/4) + o2];
            acc2[2*o2+0] = ffma2(v, w.x, acc2[2*o2+0]);
            acc2[2*o2+1] = ffma2(v, w.y, acc2[2*o2+1]);
        }
    }
    ulonglong2* xr = (ulonglong2*)(g_x + t * OUT_DIM);
#pragma unroll
    for (int o2 = 0; o2 < OUT_DIM/4; ++o2) {
        ulonglong2 r; r.x = acc2[2*o2+0]; r.y = acc2[2*o2+1];
        xr[o2] = r;
    }
}

// ---------------------------------------------------------------------------
// Kernel 2: edge MLP on tensor cores (tf32 mma.sync.m16n8k8).
// One warp = one node = 16 edges (M dim). Mean over K = row-sum of M.
// Block = 256 threads = 8 warps = 8 nodes.
// smem: wfrag copy (8704 f) + 8 warp-private work buffers 16 x 72 floats.
// ---------------------------------------------------------------------------
#define WBS 72                       // work-buffer row stride (floats)
#define EDGE_SMEM_FLOATS (WF_TOTAL + 8 * 16 * WBS)  // 8704 + 9216 = 17920
#define EDGE_SMEM_BYTES (EDGE_SMEM_FLOATS * 4)      // 71680

__global__ __launch_bounds__(256) void edge_kernel(
    const float* __restrict__ igrid,
    const float* __restrict__ ogrid,
    const int*   __restrict__ nidx,
    float* __restrict__ out)
{
    extern __shared__ float sm[];
    float* wf = sm;                                   // fragment weights
    int tid = threadIdx.x;
    int warp = tid >> 5;
    int lane = tid & 31;
    float* wb = sm + WF_TOTAL + warp * (16 * WBS);    // warp-private buffer

    // copy packed weights to smem
    {
        const float4* src = (const float4*)g_wfrag;
        float4* dst = (float4*)wf;
        for (int i = tid; i < WF_TOTAL / 4; i += 256) dst[i] = src[i];
    }
    __syncthreads();

    int node = blockIdx.x * 8 + warp;      // 0 .. B*N-1
    int b = node >> 15;
    int n = node & (NN - 1);

    int gid = lane >> 2;    // groupID (row base)
    int t0 = lane & 3;      // threadID in group

    // ---- Stage agg rows: 16 edges x 40 cols (36 + 4 zero pad), tf32 in smem.
    {
        int r = lane >> 1, half = lane & 1;
        int nb = nidx[n * KK + r];
        const float4* xrow = (const float4*)(g_x + (b * NN + nb) * OUT_DIM);
        uint* rowp = (uint*)(wb + r * WBS);
        if (half == 0) {
            uint4 p;
            p.x = tf32cvt(igrid[nb * 2 + 0]);
            p.y = tf32cvt(igrid[nb * 2 + 1]);
            p.z = tf32cvt(ogrid[n * 2 + 0]);
            p.w = tf32cvt(ogrid[n * 2 + 1]);
            ((uint4*)rowp)[0] = p;
#pragma unroll
            for (int j = 0; j < 4; ++j) {
                float4 v = xrow[j];
                uint4 q; q.x = tf32cvt(v.x); q.y = tf32cvt(v.y);
                q.z = tf32cvt(v.z); q.w = tf32cvt(v.w);
                ((uint4*)(rowp + 4 + 4*j))[0] = q;
            }
            uint4 z; z.x = z.y = z.z = z.w = 0;
            ((uint4*)(rowp + 36))[0] = z;
        } else {
#pragma unroll
            for (int j = 4; j < 8; ++j) {
                float4 v = xrow[j];
                uint4 q; q.x = tf32cvt(v.x); q.y = tf32cvt(v.y);
                q.z = tf32cvt(v.z); q.w = tf32cvt(v.w);
                ((uint4*)(rowp + 4 + 4*j))[0] = q;
            }
        }
    }
    __syncwarp();

    const uint* wbu = (const uint*)wb;
    float c[8][4];

    // ---- GEMM1: (16x40) @ W1(40x64) + bk1
#pragma unroll
    for (int nt = 0; nt < 8; ++nt) {
        float b0 = cbk1[nt * 8 + 2 * t0], b1 = cbk1[nt * 8 + 2 * t0 + 1];
        c[nt][0] = b0; c[nt][1] = b1; c[nt][2] = b0; c[nt][3] = b1;
    }
#pragma unroll
    for (int kt = 0; kt < 5; ++kt) {
        const uint* ap = wbu + gid * WBS + kt * 8 + t0;
        uint a0 = ap[0], a2 = ap[4];
        uint a1 = ap[8 * WBS], a3 = ap[8 * WBS + 4];
#pragma unroll
        for (int nt = 0; nt < 8; ++nt) {
            uint2 bb = *(const uint2*)(wf + W1F_OFF + (kt * 8 + nt) * 64 + lane * 2);
            mma_tf32(c[nt][0], c[nt][1], c[nt][2], c[nt][3], a0, a1, a2, a3, bb.x, bb.y);
        }
    }

    // ---- boundary 1: gelu -> tf32 -> work buffer (h1: 16 x 64)
    __syncwarp();
#pragma unroll
    for (int nt = 0; nt < 8; ++nt) {
        uint2 lo, hi;
        lo.x = tf32cvt(gelu_exact(c[nt][0]));
        lo.y = tf32cvt(gelu_exact(c[nt][1]));
        hi.x = tf32cvt(gelu_exact(c[nt][2]));
        hi.y = tf32cvt(gelu_exact(c[nt][3]));
        uint* p = (uint*)(wb + gid * WBS + nt * 8 + 2 * t0);
        *(uint2*)p = lo;
        *(uint2*)(p + 8 * WBS) = hi;
    }
    __syncwarp();

    // ---- GEMM2: (16x64) @ W2(64x64) + bk2
#pragma unroll
    for (int nt = 0; nt < 8; ++nt) {
        float b0 = cbk2[nt * 8 + 2 * t0], b1 = cbk2[nt * 8 + 2 * t0 + 1];
        c[nt][0] = b0; c[nt][1] = b1; c[nt][2] = b0; c[nt][3] = b1;
    }
#pragma unroll
    for (int kt = 0; kt < 8; ++kt) {
        const uint* ap = wbu + gid * WBS + kt * 8 + t0;
        uint a0 = ap[0], a2 = ap[4];
        uint a1 = ap[8 * WBS], a3 = ap[8 * WBS + 4];
#pragma unroll
        for (int nt = 0; nt < 8; ++nt) {
            uint2 bb = *(const uint2*)(wf + W2F_OFF + (kt * 8 + nt) * 64 + lane * 2);
            mma_tf32(c[nt][0], c[nt][1], c[nt][2], c[nt][3], a0, a1, a2, a3, bb.x, bb.y);
        }
    }

    // ---- boundary 2: gelu -> tf32 -> work buffer (h2: 16 x 64)
    __syncwarp();
#pragma unroll
    for (int nt = 0; nt < 8; ++nt) {
        uint2 lo, hi;
        lo.x = tf32cvt(gelu_exact(c[nt][0]));
        lo.y = tf32cvt(gelu_exact(c[nt][1]));
        hi.x = tf32cvt(gelu_exact(c[nt][2]));
        hi.y = tf32cvt(gelu_exact(c[nt][3]));
        uint* p = (uint*)(wb + gid * WBS + nt * 8 + 2 * t0);
        *(uint2*)p = lo;
        *(uint2*)(p + 8 * WBS) = hi;
    }
    __syncwarp();

    // ---- GEMM3: (16x64) @ W3(64x32) + bk3
    float c3[4][4];
#pragma unroll
    for (int nt = 0; nt < 4; ++nt) {
        float b0 = cbk3[nt * 8 + 2 * t0], b1 = cbk3[nt * 8 + 2 * t0 + 1];
        c3[nt][0] = b0; c3[nt][1] = b1; c3[nt][2] = b0; c3[nt][3] = b1;
    }
#pragma unroll
    for (int kt = 0; kt < 8; ++kt) {
        const uint* ap = wbu + gid * WBS + kt * 8 + t0;
        uint a0 = ap[0], a2 = ap[4];
        uint a1 = ap[8 * WBS], a3 = ap[8 * WBS + 4];
#pragma unroll
        for (int nt = 0; nt < 4; ++nt) {
            uint2 bb = *(const uint2*)(wf + W3F_OFF + (kt * 4 + nt) * 64 + lane * 2);
            mma_tf32(c3[nt][0], c3[nt][1], c3[nt][2], c3[nt][3], a0, a1, a2, a3, bb.x, bb.y);
        }
    }

    // ---- Mean over K = sum over 16 rows of the 16x32 tile
    float s[8];
#pragma unroll
    for (int nt = 0; nt < 4; ++nt) {
        s[2*nt + 0] = c3[nt][0] + c3[nt][2];
        s[2*nt + 1] = c3[nt][1] + c3[nt][3];
    }
#pragma unroll
    for (int off = 4; off <= 16; off <<= 1) {
#pragma unroll
        for (int i = 0; i < 8; ++i)
            s[i] += __shfl_xor_sync(0xffffffffu, s[i], off);
    }
    // lane holds col sums for cols { nt*8 + 2*t0, +1 }, replicated across gid.

    // ---- residual + LayerNorm epilogue (valid work in gid==0 lanes)
    float o[8];
    if (gid == 0) {
#pragma unroll
        for (int nt = 0; nt < 4; ++nt) {
            float2 xv = *(const float2*)(g_x + node * OUT_DIM + nt * 8 + 2 * t0);
            o[2*nt + 0] = fmaf(s[2*nt + 0], 0.0625f, xv.x);
            o[2*nt + 1] = fmaf(s[2*nt + 1], 0.0625f, xv.y);
        }
    } else {
#pragma unroll
        for (int i = 0; i < 8; ++i) o[i] = 0.0f;
    }
    float part = 0.0f;
#pragma unroll
    for (int i = 0; i < 8; ++i) part += o[i];
    part += __shfl_xor_sync(0xffffffffu, part, 1);
    part += __shfl_xor_sync(0xffffffffu, part, 2);
    float mu = part * (1.0f / OUT_DIM);
    float vp = 0.0f;
#pragma unroll
    for (int i = 0; i < 8; ++i) { float d = o[i] - mu; vp = fmaf(d, d, vp); }
    vp += __shfl_xor_sync(0xffffffffu, vp, 1);
    vp += __shfl_xor_sync(0xffffffffu, vp, 2);
    if (gid == 0) {
        float rs = rsqrtf(vp * (1.0f / OUT_DIM) + 1e-5f);
#pragma unroll
        for (int nt = 0; nt < 4; ++nt) {
            int col = nt * 8 + 2 * t0;
            float2 y;
            y.x = fmaf((o[2*nt + 0] - mu) * rs, cG[col + 0], cBt[col + 0]);
            y.y = fmaf((o[2*nt + 1] - mu) * rs, cG[col + 1], cBt[col + 1]);
            *(float2*)(out + node * OUT_DIM + col) = y;
        }
    }
}

// ---------------------------------------------------------------------------
extern "C" void kernel_launch(void* const* d_in, const int* in_sizes, int n_in,
                              void* d_out, int out_size) {
    const float* inp   = (const float*)d_in[0];
    const float* igrid = (const float*)d_in[1];
    const float* ogrid = (const float*)d_in[2];
    const int*   nidx  = (const int*)  d_in[3];
    const float* Wp1   = (const float*)d_in[4];
    const float* bp1   = (const float*)d_in[5];
    const float* Wp2   = (const float*)d_in[6];
    const float* bp2   = (const float*)d_in[7];
    const float* Wk1   = (const float*)d_in[8];
    const float* bk1   = (const float*)d_in[9];
    const float* Wk2   = (const float*)d_in[10];
    const float* bk2   = (const float*)d_in[11];
    const float* Wk3   = (const float*)d_in[12];
    const float* bk3   = (const float*)d_in[13];
    const float* ln_g  = (const float*)d_in[14];
    const float* ln_b  = (const float*)d_in[15];
    float* out = (float*)d_out;

    static int smem_set = 0;
    if (!smem_set) {
        cudaFuncSetAttribute(edge_kernel,
                             cudaFuncAttributeMaxDynamicSharedMemorySize,
                             EDGE_SMEM_BYTES);
        smem_set = 1;
    }

    cudaMemcpyToSymbolAsync(cbk1, bk1, KH * sizeof(float), 0, cudaMemcpyDeviceToDevice);
    cudaMemcpyToSymbolAsync(cbk2, bk2, KH * sizeof(float), 0, cudaMemcpyDeviceToDevice);
    cudaMemcpyToSymbolAsync(cbk3, bk3, OUT_DIM * sizeof(float), 0, cudaMemcpyDeviceToDevice);
    cudaMemcpyToSymbolAsync(cG,   ln_g, OUT_DIM * sizeof(float), 0, cudaMemcpyDeviceToDevice);
    cudaMemcpyToSymbolAsync(cBt,  ln_b, OUT_DIM * sizeof(float), 0, cudaMemcpyDeviceToDevice);
    cudaMemcpyToSymbolAsync(cWp1, Wp1, IN_DIM * HID * sizeof(float), 0, cudaMemcpyDeviceToDevice);
    cudaMemcpyToSymbolAsync(cWp2, Wp2, HID * OUT_DIM * sizeof(float), 0, cudaMemcpyDeviceToDevice);
    cudaMemcpyToSymbolAsync(cbp1, bp1, HID * sizeof(float), 0, cudaMemcpyDeviceToDevice);
    cudaMemcpyToSymbolAsync(cbp2, bp2, OUT_DIM * sizeof(float), 0, cudaMemcpyDeviceToDevice);

    pack_weights<<<1, 256>>>(Wk1, Wk2, Wk3);
    pointwise_kernel<<<(BB * NN) / 256, 256>>>(inp);
    edge_kernel<<<(BB * NN) / 8, 256, EDGE_SMEM_BYTES>>>(igrid, ogrid, nidx, out);
}

// round 7
// speedup vs baseline: 2.7255x; 1.0878x over previous
#include <cuda_runtime.h>
#include <math.h>
#include <stdint.h>

// Problem constants
#define BB 4
#define NN 32768
#define KK 16
#define IN_DIM 32
#define HID 64
#define OUT_DIM 32
#define KIN 36
#define KH 64

typedef unsigned long long ull;
typedef unsigned int uint;

// Scratch: pointwise-MLP output x (B,N,32) = 16 MB, + fragment-packed weights
__device__ float g_x[BB * NN * OUT_DIM];

// Fragment-packed tf32 weights, PAIR layout: tiles (2p, 2p+1) share a 128-word
// block; word = p*128 + lane*4 + r, r0..r3 = {b0,b1 of tile 2p, b0,b1 of 2p+1}.
// One LDS.128 per lane yields both tiles' B fragments.
#define W1F_OFF 0
#define W1F_SIZE (5 * 8 * 64)     // 2560
#define W2F_OFF (W1F_OFF + W1F_SIZE)
#define W2F_SIZE (8 * 8 * 64)     // 4096
#define W3F_OFF (W2F_OFF + W2F_SIZE)
#define W3F_SIZE (8 * 4 * 64)     // 2048
#define WF_TOTAL (W3F_OFF + W3F_SIZE)  // 8704 floats
__device__ float g_wfrag[WF_TOTAL];

// Small params in constant bank
__constant__ float cbk1[KH];
__constant__ float cbk2[KH];
__constant__ float cbk3[OUT_DIM];
__constant__ float cG[OUT_DIM];
__constant__ float cBt[OUT_DIM];
__constant__ ulonglong2 cWp1[IN_DIM * HID / 4];
__constant__ ulonglong2 cWp2[HID * OUT_DIM / 4];
__constant__ float cbp1[HID];
__constant__ float cbp2[OUT_DIM];

// ---------------- helpers ----------------
__device__ __forceinline__ ull ffma2(ull a, ull b, ull c) {
    ull d;
    asm("fma.rn.f32x2 %0, %1, %2, %3;" : "=l"(d) : "l"(a), "l"(b), "l"(c));
    return d;
}
__device__ __forceinline__ ull pack_dup(float v) {
    ull d;
    asm("mov.b64 %0, {%1, %1};" : "=l"(d) : "r"(__float_as_uint(v)));
    return d;
}
__device__ __forceinline__ ull pack2(float lo, float hi) {
    ull d;
    asm("mov.b64 %0, {%1, %2};" : "=l"(d) : "r"(__float_as_uint(lo)), "r"(__float_as_uint(hi)));
    return d;
}
__device__ __forceinline__ void unpack2(ull p, float& lo, float& hi) {
    uint a, b;
    asm("mov.b64 {%0, %1}, %2;" : "=r"(a), "=r"(b) : "l"(p));
    lo = __uint_as_float(a); hi = __uint_as_float(b);
}
// Branchless gelu: Abramowitz-Stegun 7.1.26 erf (|eps| <= 1.5e-7), 2 MUFU.
__device__ __forceinline__ float gelu_fast(float x) {
    float z  = 0.7071067811865476f * x;
    float az = fabsf(z);
    float d  = fmaf(0.3275911f, az, 1.0f);
    float t;
    asm("rcp.approx.f32 %0, %1;" : "=f"(t) : "f"(d));
    float p  = fmaf(1.061405429f, t, -1.453152027f);
    p = fmaf(p, t, 1.421413741f);
    p = fmaf(p, t, -0.284496736f);
    p = fmaf(p, t, 0.254829592f);
    p = p * t;
    float e  = __expf(-az * az);
    float er = fmaf(-p, e, 1.0f);    // erf(|z|)
    er = copysignf(er, z);
    float hx = 0.5f * x;
    return fmaf(hx, er, hx);
}
__device__ __forceinline__ uint tf32cvt(float f) {
    uint u;
    asm("cvt.rna.tf32.f32 %0, %1;" : "=r"(u) : "f"(f));
    return u;
}
__device__ __forceinline__ void mma_tf32(
    float& c0, float& c1, float& c2, float& c3,
    uint a0, uint a1, uint a2, uint a3, uint b0, uint b1)
{
    asm("mma.sync.aligned.m16n8k8.row.col.f32.tf32.tf32.f32 "
        "{%0,%1,%2,%3}, {%4,%5,%6,%7}, {%8,%9}, {%0,%1,%2,%3};"
        : "+f"(c0), "+f"(c1), "+f"(c2), "+f"(c3)
        : "r"(a0), "r"(a1), "r"(a2), "r"(a3), "r"(b0), "r"(b1));
}

// ---------------------------------------------------------------------------
// Kernel 0: pack weights into PAIRED mma B-fragment order (tf32).
// Word index i: pair p = i>>7, lane = (i&127)>>2, r = i&3.
// tile = 2p + (r>>1), reg = r&1. k = kt*8 + (lane&3) + reg*4, n = nt*8 + lane/4.
// ---------------------------------------------------------------------------
__global__ void pack_weights(const float* __restrict__ Wk1,
                             const float* __restrict__ Wk2,
                             const float* __restrict__ Wk3)
{
    int tid = blockIdx.x * 256 + threadIdx.x;
    int stride = gridDim.x * 256;
    for (int i = tid; i < W1F_SIZE; i += stride) {
        int p = i >> 7, lane = (i & 127) >> 2, r = i & 3;
        int tile = 2 * p + (r >> 1), reg = r & 1;
        int kt = tile >> 3, nt = tile & 7;
        int k = kt * 8 + (lane & 3) + reg * 4;
        int n = nt * 8 + (lane >> 2);
        float v = (k < KIN) ? Wk1[k * KH + n] : 0.0f;
        g_wfrag[W1F_OFF + i] = __uint_as_float(tf32cvt(v));
    }
    for (int i = tid; i < W2F_SIZE; i += stride) {
        int p = i >> 7, lane = (i & 127) >> 2, r = i & 3;
        int tile = 2 * p + (r >> 1), reg = r & 1;
        int kt = tile >> 3, nt = tile & 7;
        int k = kt * 8 + (lane & 3) + reg * 4;
        int n = nt * 8 + (lane >> 2);
        g_wfrag[W2F_OFF + i] = __uint_as_float(tf32cvt(Wk2[k * KH + n]));
    }
    for (int i = tid; i < W3F_SIZE; i += stride) {
        int p = i >> 7, lane = (i & 127) >> 2, r = i & 3;
        int tile = 2 * p + (r >> 1), reg = r & 1;
        int kt = tile >> 2, nt = tile & 3;
        int k = kt * 8 + (lane & 3) + reg * 4;
        int n = nt * 8 + (lane >> 2);
        g_wfrag[W3F_OFF + i] = __uint_as_float(tf32cvt(Wk3[k * OUT_DIM + n]));
    }
}

// ---------------------------------------------------------------------------
// Kernel 1: pointwise MLP (FFMA2, const weights)
// ---------------------------------------------------------------------------
__global__ __launch_bounds__(256) void pointwise_kernel(
    const float* __restrict__ inp)
{
    int t = blockIdx.x * 256 + threadIdx.x;
    const float4* ir = (const float4*)(inp + t * IN_DIM);

    float in[IN_DIM];
#pragma unroll
    for (int i = 0; i < IN_DIM / 4; ++i) {
        float4 v = ir[i];
        in[4*i+0] = v.x; in[4*i+1] = v.y; in[4*i+2] = v.z; in[4*i+3] = v.w;
    }

    ull acc[HID/2];
#pragma unroll
    for (int i = 0; i < HID/2; ++i) acc[i] = pack2(cbp1[2*i], cbp1[2*i+1]);
#pragma unroll
    for (int c = 0; c < IN_DIM; ++c) {
        ull v = pack_dup(in[c]);
#pragma unroll
        for (int o2 = 0; o2 < HID/4; ++o2) {
            ulonglong2 w = cWp1[c * (HID/4) + o2];
            acc[2*o2+0] = ffma2(v, w.x, acc[2*o2+0]);
            acc[2*o2+1] = ffma2(v, w.y, acc[2*o2+1]);
        }
    }
    float h[HID];
#pragma unroll
    for (int i = 0; i < HID/2; ++i) {
        float a, b; unpack2(acc[i], a, b);
        h[2*i] = gelu_fast(a); h[2*i+1] = gelu_fast(b);
    }

    ull acc2[OUT_DIM/2];
#pragma unroll
    for (int i = 0; i < OUT_DIM/2; ++i) acc2[i] = pack2(cbp2[2*i], cbp2[2*i+1]);
#pragma unroll
    for (int c = 0; c < HID; ++c) {
        ull v = pack_dup(h[c]);
#pragma unroll
        for (int o2 = 0; o2 < OUT_DIM/4; ++o2) {
            ulonglong2 w = cWp2[c * (OUT_DIM/4) + o2];
            acc2[2*o2+0] = ffma2(v, w.x, acc2[2*o2+0]);
            acc2[2*o2+1] = ffma2(v, w.y, acc2[2*o2+1]);
        }
    }
    ulonglong2* xr = (ulonglong2*)(g_x + t * OUT_DIM);
#pragma unroll
    for (int o2 = 0; o2 < OUT_DIM/4; ++o2) {
        ulonglong2 r; r.x = acc2[2*o2+0]; r.y = acc2[2*o2+1];
        xr[o2] = r;
    }
}

// ---------------------------------------------------------------------------
// Kernel 2: edge MLP on tensor cores (tf32 mma.sync.m16n8k8).
// One warp = one node = 16 edges (M). Mean over K = row-sum of M.
// B fragments: one LDS.128 per lane covers two n-tiles.
// ---------------------------------------------------------------------------
#define WBS 72
#define EDGE_SMEM_FLOATS (WF_TOTAL + 8 * 16 * WBS)  // 17920
#define EDGE_SMEM_BYTES (EDGE_SMEM_FLOATS * 4)      // 71680

__global__ __launch_bounds__(256) void edge_kernel(
    const float* __restrict__ igrid,
    const float* __restrict__ ogrid,
    const int*   __restrict__ nidx,
    float* __restrict__ out)
{
    extern __shared__ float sm[];
    float* wf = sm;
    int tid = threadIdx.x;
    int warp = tid >> 5;
    int lane = tid & 31;
    float* wb = sm + WF_TOTAL + warp * (16 * WBS);

    {
        const float4* src = (const float4*)g_wfrag;
        float4* dst = (float4*)wf;
        for (int i = tid; i < WF_TOTAL / 4; i += 256) dst[i] = src[i];
    }
    __syncthreads();

    int node = blockIdx.x * 8 + warp;
    int b = node >> 15;
    int n = node & (NN - 1);

    int gid = lane >> 2;
    int t0 = lane & 3;

    // ---- Stage agg rows: 16 edges x 40 cols (36 + 4 zero pad), tf32.
    {
        int r = lane >> 1, half = lane & 1;
        int nb = nidx[n * KK + r];
        const float4* xrow = (const float4*)(g_x + (b * NN + nb) * OUT_DIM);
        uint* rowp = (uint*)(wb + r * WBS);
        if (half == 0) {
            uint4 p;
            p.x = tf32cvt(igrid[nb * 2 + 0]);
            p.y = tf32cvt(igrid[nb * 2 + 1]);
            p.z = tf32cvt(ogrid[n * 2 + 0]);
            p.w = tf32cvt(ogrid[n * 2 + 1]);
            ((uint4*)rowp)[0] = p;
#pragma unroll
            for (int j = 0; j < 4; ++j) {
                float4 v = xrow[j];
                uint4 q; q.x = tf32cvt(v.x); q.y = tf32cvt(v.y);
                q.z = tf32cvt(v.z); q.w = tf32cvt(v.w);
                ((uint4*)(rowp + 4 + 4*j))[0] = q;
            }
            uint4 z; z.x = z.y = z.z = z.w = 0;
            ((uint4*)(rowp + 36))[0] = z;
        } else {
#pragma unroll
            for (int j = 4; j < 8; ++j) {
                float4 v = xrow[j];
                uint4 q; q.x = tf32cvt(v.x); q.y = tf32cvt(v.y);
                q.z = tf32cvt(v.z); q.w = tf32cvt(v.w);
                ((uint4*)(rowp + 4 + 4*j))[0] = q;
            }
        }
    }
    __syncwarp();

    const uint* wbu = (const uint*)wb;
    float c[8][4];

    // ---- GEMM1: (16x40) @ W1(40x64) + bk1
#pragma unroll
    for (int nt = 0; nt < 8; ++nt) {
        float b0 = cbk1[nt * 8 + 2 * t0], b1 = cbk1[nt * 8 + 2 * t0 + 1];
        c[nt][0] = b0; c[nt][1] = b1; c[nt][2] = b0; c[nt][3] = b1;
    }
#pragma unroll
    for (int kt = 0; kt < 5; ++kt) {
        const uint* ap = wbu + gid * WBS + kt * 8 + t0;
        uint a0 = ap[0], a2 = ap[4];
        uint a1 = ap[8 * WBS], a3 = ap[8 * WBS + 4];
#pragma unroll
        for (int nt2 = 0; nt2 < 4; ++nt2) {
            uint4 bb = *(const uint4*)(wf + W1F_OFF + (kt * 8 + 2 * nt2) * 64 + lane * 4);
            mma_tf32(c[2*nt2][0], c[2*nt2][1], c[2*nt2][2], c[2*nt2][3],
                     a0, a1, a2, a3, bb.x, bb.y);
            mma_tf32(c[2*nt2+1][0], c[2*nt2+1][1], c[2*nt2+1][2], c[2*nt2+1][3],
                     a0, a1, a2, a3, bb.z, bb.w);
        }
    }

    // ---- boundary 1: gelu -> tf32 -> work buffer (h1: 16 x 64)
    __syncwarp();
#pragma unroll
    for (int nt = 0; nt < 8; ++nt) {
        uint2 lo, hi;
        lo.x = tf32cvt(gelu_fast(c[nt][0]));
        lo.y = tf32cvt(gelu_fast(c[nt][1]));
        hi.x = tf32cvt(gelu_fast(c[nt][2]));
        hi.y = tf32cvt(gelu_fast(c[nt][3]));
        uint* p = (uint*)(wb + gid * WBS + nt * 8 + 2 * t0);
        *(uint2*)p = lo;
        *(uint2*)(p + 8 * WBS) = hi;
    }
    __syncwarp();

    // ---- GEMM2: (16x64) @ W2(64x64) + bk2
#pragma unroll
    for (int nt = 0; nt < 8; ++nt) {
        float b0 = cbk2[nt * 8 + 2 * t0], b1 = cbk2[nt * 8 + 2 * t0 + 1];
        c[nt][0] = b0; c[nt][1] = b1; c[nt][2] = b0; c[nt][3] = b1;
    }
#pragma unroll
    for (int kt = 0; kt < 8; ++kt) {
        const uint* ap = wbu + gid * WBS + kt * 8 + t0;
        uint a0 = ap[0], a2 = ap[4];
        uint a1 = ap[8 * WBS], a3 = ap[8 * WBS + 4];
#pragma unroll
        for (int nt2 = 0; nt2 < 4; ++nt2) {
            uint4 bb = *(const uint4*)(wf + W2F_OFF + (kt * 8 + 2 * nt2) * 64 + lane * 4);
            mma_tf32(c[2*nt2][0], c[2*nt2][1], c[2*nt2][2], c[2*nt2][3],
                     a0, a1, a2, a3, bb.x, bb.y);
            mma_tf32(c[2*nt2+1][0], c[2*nt2+1][1], c[2*nt2+1][2], c[2*nt2+1][3],
                     a0, a1, a2, a3, bb.z, bb.w);
        }
    }

    // ---- boundary 2: gelu -> tf32 -> work buffer (h2: 16 x 64)
    __syncwarp();
#pragma unroll
    for (int nt = 0; nt < 8; ++nt) {
        uint2 lo, hi;
        lo.x = tf32cvt(gelu_fast(c[nt][0]));
        lo.y = tf32cvt(gelu_fast(c[nt][1]));
        hi.x = tf32cvt(gelu_fast(c[nt][2]));
        hi.y = tf32cvt(gelu_fast(c[nt][3]));
        uint* p = (uint*)(wb + gid * WBS + nt * 8 + 2 * t0);
        *(uint2*)p = lo;
        *(uint2*)(p + 8 * WBS) = hi;
    }
    __syncwarp();

    // ---- GEMM3: (16x64) @ W3(64x32) + bk3
    float c3[4][4];
#pragma unroll
    for (int nt = 0; nt < 4; ++nt) {
        float b0 = cbk3[nt * 8 + 2 * t0], b1 = cbk3[nt * 8 + 2 * t0 + 1];
        c3[nt][0] = b0; c3[nt][1] = b1; c3[nt][2] = b0; c3[nt][3] = b1;
    }
#pragma unroll
    for (int kt = 0; kt < 8; ++kt) {
        const uint* ap = wbu + gid * WBS + kt * 8 + t0;
        uint a0 = ap[0], a2 = ap[4];
        uint a1 = ap[8 * WBS], a3 = ap[8 * WBS + 4];
#pragma unroll
        for (int nt2 = 0; nt2 < 2; ++nt2) {
            uint4 bb = *(const uint4*)(wf + W3F_OFF + (kt * 4 + 2 * nt2) * 64 + lane * 4);
            mma_tf32(c3[2*nt2][0], c3[2*nt2][1], c3[2*nt2][2], c3[2*nt2][3],
                     a0, a1, a2, a3, bb.x, bb.y);
            mma_tf32(c3[2*nt2+1][0], c3[2*nt2+1][1], c3[2*nt2+1][2], c3[2*nt2+1][3],
                     a0, a1, a2, a3, bb.z, bb.w);
        }
    }

    // ---- Mean over K = sum over 16 rows of the 16x32 tile
    float s[8];
#pragma unroll
    for (int nt = 0; nt < 4; ++nt) {
        s[2*nt + 0] = c3[nt][0] + c3[nt][2];
        s[2*nt + 1] = c3[nt][1] + c3[nt][3];
    }
#pragma unroll
    for (int off = 4; off <= 16; off <<= 1) {
#pragma unroll
        for (int i = 0; i < 8; ++i)
            s[i] += __shfl_xor_sync(0xffffffffu, s[i], off);
    }

    // ---- residual + LayerNorm epilogue (valid work in gid==0 lanes)
    float o[8];
    if (gid == 0) {
#pragma unroll
        for (int nt = 0; nt < 4; ++nt) {
            float2 xv = *(const float2*)(g_x + node * OUT_DIM + nt * 8 + 2 * t0);
            o[2*nt + 0] = fmaf(s[2*nt + 0], 0.0625f, xv.x);
            o[2*nt + 1] = fmaf(s[2*nt + 1], 0.0625f, xv.y);
        }
    } else {
#pragma unroll
        for (int i = 0; i < 8; ++i) o[i] = 0.0f;
    }
    float part = 0.0f;
#pragma unroll
    for (int i = 0; i < 8; ++i) part += o[i];
    part += __shfl_xor_sync(0xffffffffu, part, 1);
    part += __shfl_xor_sync(0xffffffffu, part, 2);
    float mu = part * (1.0f / OUT_DIM);
    float vp = 0.0f;
#pragma unroll
    for (int i = 0; i < 8; ++i) { float d = o[i] - mu; vp = fmaf(d, d, vp); }
    vp += __shfl_xor_sync(0xffffffffu, vp, 1);
    vp += __shfl_xor_sync(0xffffffffu, vp, 2);
    if (gid == 0) {
        float rs = rsqrtf(vp * (1.0f / OUT_DIM) + 1e-5f);
#pragma unroll
        for (int nt = 0; nt < 4; ++nt) {
            int col = nt * 8 + 2 * t0;
            float2 y;
            y.x = fmaf((o[2*nt + 0] - mu) * rs, cG[col + 0], cBt[col + 0]);
            y.y = fmaf((o[2*nt + 1] - mu) * rs, cG[col + 1], cBt[col + 1]);
            *(float2*)(out + node * OUT_DIM + col) = y;
        }
    }
}

// ---------------------------------------------------------------------------
extern "C" void kernel_launch(void* const* d_in, const int* in_sizes, int n_in,
                              void* d_out, int out_size) {
    const float* inp   = (const float*)d_in[0];
    const float* igrid = (const float*)d_in[1];
    const float* ogrid = (const float*)d_in[2];
    const int*   nidx  = (const int*)  d_in[3];
    const float* Wp1   = (const float*)d_in[4];
    const float* bp1   = (const float*)d_in[5];
    const float* Wp2   = (const float*)d_in[6];
    const float* bp2   = (const float*)d_in[7];
    const float* Wk1   = (const float*)d_in[8];
    const float* bk1   = (const float*)d_in[9];
    const float* Wk2   = (const float*)d_in[10];
    const float* bk2   = (const float*)d_in[11];
    const float* Wk3   = (const float*)d_in[12];
    const float* bk3   = (const float*)d_in[13];
    const float* ln_g  = (const float*)d_in[14];
    const float* ln_b  = (const float*)d_in[15];
    float* out = (float*)d_out;

    static int smem_set = 0;
    if (!smem_set) {
        cudaFuncSetAttribute(edge_kernel,
                             cudaFuncAttributeMaxDynamicSharedMemorySize,
                             EDGE_SMEM_BYTES);
        smem_set = 1;
    }

    cudaMemcpyToSymbolAsync(cbk1, bk1, KH * sizeof(float), 0, cudaMemcpyDeviceToDevice);
    cudaMemcpyToSymbolAsync(cbk2, bk2, KH * sizeof(float), 0, cudaMemcpyDeviceToDevice);
    cudaMemcpyToSymbolAsync(cbk3, bk3, OUT_DIM * sizeof(float), 0, cudaMemcpyDeviceToDevice);
    cudaMemcpyToSymbolAsync(cG,   ln_g, OUT_DIM * sizeof(float), 0, cudaMemcpyDeviceToDevice);
    cudaMemcpyToSymbolAsync(cBt,  ln_b, OUT_DIM * sizeof(float), 0, cudaMemcpyDeviceToDevice);
    cudaMemcpyToSymbolAsync(cWp1, Wp1, IN_DIM * HID * sizeof(float), 0, cudaMemcpyDeviceToDevice);
    cudaMemcpyToSymbolAsync(cWp2, Wp2, HID * OUT_DIM * sizeof(float), 0, cudaMemcpyDeviceToDevice);
    cudaMemcpyToSymbolAsync(cbp1, bp1, HID * sizeof(float), 0, cudaMemcpyDeviceToDevice);
    cudaMemcpyToSymbolAsync(cbp2, bp2, OUT_DIM * sizeof(float), 0, cudaMemcpyDeviceToDevice);

    pack_weights<<<32, 256>>>(Wk1, Wk2, Wk3);
    pointwise_kernel<<<(BB * NN) / 256, 256>>>(inp);
    edge_kernel<<<(BB * NN) / 8, 256, EDGE_SMEM_BYTES>>>(igrid, ogrid, nidx, out);
}